// round 14
// baseline (speedup 1.0000x reference)
#include <cuda_runtime.h>
#include <cuda_fp16.h>
#include <cstdint>

// Problem constants
#define N_TOK 8192
#define C_DIM 1024
#define F_DIM 4096
#define E_NUM 8
#define S_SLOTS (N_TOK * 2)
#define CAP 2048

// ---------------- scratch (static device globals) ----------------------------
__device__ __half g_disp[(size_t)E_NUM * CAP * C_DIM];   // 32 MB fp16
__device__ __half g_h[(size_t)E_NUM * CAP * F_DIM];      // 128 MB fp16
__device__ __half g_y[(size_t)E_NUM * CAP * C_DIM];      // 32 MB fp16
__device__ __half g_W1h[(size_t)E_NUM * F_DIM * C_DIM];  // W1^T per expert [F][C] fp16
__device__ __half g_W2h[(size_t)E_NUM * C_DIM * F_DIM];  // W2^T per expert [C][F] fp16
__device__ int    g_eidx[S_SLOTS];
__device__ float  g_wf[S_SLOTS];
__device__ int    g_loc[S_SLOTS];
__device__ int    g_cnt[E_NUM];
__device__ float  g_probs_sum[E_NUM];

// ---------------- helpers ----------------------------------------------------
__device__ __forceinline__ float gelu_tanh(float x) {
    const float k0 = 0.7978845608028654f;
    float x3 = x * x * x;
    float t = tanhf(k0 * (x + 0.044715f * x3));
    return 0.5f * x * (1.0f + t);
}

// fp16 m16n8k16, fp32 accumulate
__device__ __forceinline__ void mma_f16(float* d, const uint32_t* a, const uint32_t* b) {
    asm volatile(
        "mma.sync.aligned.m16n8k16.row.col.f32.f16.f16.f32 "
        "{%0,%1,%2,%3}, {%4,%5,%6,%7}, {%8,%9}, {%0,%1,%2,%3};"
        : "+f"(d[0]), "+f"(d[1]), "+f"(d[2]), "+f"(d[3])
        : "r"(a[0]), "r"(a[1]), "r"(a[2]), "r"(a[3]), "r"(b[0]), "r"(b[1]));
}

__device__ __forceinline__ void cp_async16(uint32_t smem_dst, const void* gmem_src) {
    asm volatile("cp.async.cg.shared.global [%0], [%1], 16;\n" :: "r"(smem_dst), "l"(gmem_src));
}
__device__ __forceinline__ void cp_commit() {
    asm volatile("cp.async.commit_group;\n");
}
template <int N>
__device__ __forceinline__ void cp_wait() {
    asm volatile("cp.async.wait_group %0;\n" :: "n"(N));
}

// ---------------- init -------------------------------------------------------
__global__ void init_kernel() {
    int t = threadIdx.x;
    if (t < E_NUM) g_probs_sum[t] = 0.0f;
}

// ---------------- fused prep: gating first, then W1/W2 transpose-convert -------
__device__ __forceinline__ void transpose_tile(const float* __restrict__ src,
                                               __half* __restrict__ dst,
                                               int K, int N, int bx, int by, int e,
                                               int tid, float* t /* 64x65 */) {
    const float* s = src + (size_t)e * K * N;
    __half* d = dst + (size_t)e * N * K;
    int n0 = bx * 64, k0 = by * 64;

    {
        int r = tid >> 4, c4 = tid & 15;
#pragma unroll
        for (int p = 0; p < 4; p++) {
            float4 v = *(const float4*)(s + (size_t)(k0 + r + p * 16) * N + n0 + c4 * 4);
            float* row = t + (r + p * 16) * 65 + c4 * 4;
            row[0] = v.x; row[1] = v.y; row[2] = v.z; row[3] = v.w;
        }
    }
    __syncthreads();
    {
        int n = tid >> 3, c8 = tid & 7;
#pragma unroll
        for (int p = 0; p < 2; p++) {
            int nn = n + p * 32;
            __half2 h[4];
#pragma unroll
            for (int j = 0; j < 4; j++)
                h[j] = __floats2half2_rn(t[(c8 * 8 + 2 * j) * 65 + nn],
                                         t[(c8 * 8 + 2 * j + 1) * 65 + nn]);
            *(uint4*)(d + (size_t)(n0 + nn) * K + k0 + c8 * 8) = *(uint4*)h;
        }
    }
}

__device__ __forceinline__ void gate_block(const float* __restrict__ x,
                                           const float* __restrict__ w_gate,
                                           const float* __restrict__ b_gate,
                                           int blk, int tid, float* sprob) {
    if (tid < E_NUM) sprob[tid] = 0.0f;
    __syncthreads();

    int warp = tid >> 5, lane = tid & 31;
    int n = blk * 8 + warp;
    const float* xr = x + (size_t)n * C_DIM;

    float acc[E_NUM];
#pragma unroll
    for (int e = 0; e < E_NUM; e++) acc[e] = 0.0f;

    for (int c = lane; c < C_DIM; c += 32) {
        float xv = xr[c];
        const float4* w4 = (const float4*)(w_gate + (size_t)c * E_NUM);
        float4 wa = w4[0], wb = w4[1];
        acc[0] += xv * wa.x; acc[1] += xv * wa.y;
        acc[2] += xv * wa.z; acc[3] += xv * wa.w;
        acc[4] += xv * wb.x; acc[5] += xv * wb.y;
        acc[6] += xv * wb.z; acc[7] += xv * wb.w;
    }
#pragma unroll
    for (int e = 0; e < E_NUM; e++)
#pragma unroll
        for (int o = 16; o > 0; o >>= 1)
            acc[e] += __shfl_down_sync(0xffffffffu, acc[e], o);

    if (lane == 0) {
        float p[E_NUM];
        float mx = -1e30f;
#pragma unroll
        for (int e = 0; e < E_NUM; e++) { p[e] = acc[e] + b_gate[e]; mx = fmaxf(mx, p[e]); }
        float s = 0.0f;
#pragma unroll
        for (int e = 0; e < E_NUM; e++) { p[e] = expf(p[e] - mx); s += p[e]; }
        float inv = 1.0f / s;
#pragma unroll
        for (int e = 0; e < E_NUM; e++) p[e] *= inv;

        int i0 = 0;
#pragma unroll
        for (int e = 1; e < E_NUM; e++) if (p[e] > p[i0]) i0 = e;
        int i1 = (i0 == 0) ? 1 : 0;
#pragma unroll
        for (int e = 0; e < E_NUM; e++) if (e != i0 && p[e] > p[i1]) i1 = e;

        float w0 = p[i0], w1 = p[i1];
        float ws = w0 + w1 + 1e-9f;
        g_eidx[2 * n]     = i0;
        g_eidx[2 * n + 1] = i1;
        g_wf[2 * n]       = w0 / ws;
        g_wf[2 * n + 1]   = w1 / ws;
#pragma unroll
        for (int e = 0; e < E_NUM; e++) atomicAdd(&sprob[e], p[e]);
    }
    __syncthreads();
    if (tid < E_NUM) atomicAdd(&g_probs_sum[tid], sprob[tid]);
}

__global__ void prep_kernel(const float* __restrict__ W1, const float* __restrict__ W2,
                            const float* __restrict__ x,
                            const float* __restrict__ w_gate,
                            const float* __restrict__ b_gate) {
    __shared__ float shbuf[64 * 65];
    int bid = blockIdx.x;
    int tid = threadIdx.x;
    if (bid < 1024) {
        gate_block(x, w_gate, b_gate, bid, tid, shbuf);
    } else if (bid < 1024 + 8192) {
        int b1 = bid - 1024;
        int e = b1 >> 10;
        int rem = b1 & 1023;
        int bx = rem & 63, by = rem >> 6;
        transpose_tile(W1, g_W1h, C_DIM, F_DIM, bx, by, e, tid, shbuf);
    } else {
        int b2 = bid - 1024 - 8192;
        int e = b2 >> 10;
        int rem = b2 & 1023;
        int bx = rem & 15, by = rem >> 4;
        transpose_tile(W2, g_W2h, F_DIM, C_DIM, bx, by, e, tid, shbuf);
    }
}

// ---------------- FCFS capacity scan + aux loss --------------------------------
__global__ void scan_kernel(float* __restrict__ d_out, int out_size) {
    const int PER = 64;
    int t = threadIdx.x;
    int base = t * PER;

    int cnt[E_NUM];
#pragma unroll
    for (int e = 0; e < E_NUM; e++) cnt[e] = 0;
    for (int i = 0; i < PER; i++) cnt[g_eidx[base + i]]++;

    unsigned long long lo = 0, hi = 0;
#pragma unroll
    for (int e = 0; e < 4; e++) {
        lo |= (unsigned long long)cnt[e] << (16 * e);
        hi |= (unsigned long long)cnt[e + 4] << (16 * e);
    }

    __shared__ unsigned long long s0[256], s1[256];
    s0[t] = lo; s1[t] = hi;
    __syncthreads();
    for (int off = 1; off < 256; off <<= 1) {
        unsigned long long v0 = 0, v1 = 0;
        if (t >= off) { v0 = s0[t - off]; v1 = s1[t - off]; }
        __syncthreads();
        s0[t] += v0; s1[t] += v1;
        __syncthreads();
    }
    unsigned long long p0 = (t > 0) ? s0[t - 1] : 0ULL;
    unsigned long long p1 = (t > 0) ? s1[t - 1] : 0ULL;

    int exc[E_NUM];
#pragma unroll
    for (int e = 0; e < 4; e++) {
        exc[e]     = (int)((p0 >> (16 * e)) & 0xffffULL);
        exc[e + 4] = (int)((p1 >> (16 * e)) & 0xffffULL);
    }
    for (int i = 0; i < PER; i++) {
        int s = base + i;
        int e = g_eidx[s];
        int pos = exc[e]++;
        g_loc[s] = (pos < CAP) ? (e * CAP + pos) : -1;
    }

    if (t == 0) {
        unsigned long long t0 = s0[255], t1 = s1[255];
        float sumload = 0.0f, load[E_NUM];
#pragma unroll
        for (int e = 0; e < 4; e++) {
            int c0 = (int)((t0 >> (16 * e)) & 0xffffULL);
            int c1 = (int)((t1 >> (16 * e)) & 0xffffULL);
            g_cnt[e]     = min(c0, CAP);
            g_cnt[e + 4] = min(c1, CAP);
            load[e]     = (float)min(c0, CAP);
            load[e + 4] = (float)min(c1, CAP);
        }
#pragma unroll
        for (int e = 0; e < E_NUM; e++) sumload += load[e];
        float fe[E_NUM], sfe = 0.0f;
#pragma unroll
        for (int e = 0; e < E_NUM; e++) { fe[e] = g_probs_sum[e] / (float)N_TOK; sfe += fe[e]; }
        float aux = 0.0f;
#pragma unroll
        for (int e = 0; e < E_NUM; e++) {
            float fn = fe[e] / (sfe + 1e-9f);
            float fa = load[e] / (sumload + 1e-9f);
            float d = fn - fa;
            aux += d * d;
        }
        aux = 0.01f * aux / (float)E_NUM;
        if (out_size > N_TOK * C_DIM)
            d_out[(size_t)N_TOK * C_DIM] = aux;
    }
}

// ---------------- dispatch gather (fp16 convert at write) ----------------------
__global__ void dispatch_kernel(const float* __restrict__ x) {
    int s = blockIdx.x;
    int loc = g_loc[s];
    if (loc < 0) return;
    const float4* src = (const float4*)(x + ((size_t)(s >> 1)) * C_DIM);
    __half* dst = g_disp + (size_t)loc * C_DIM;
    int t = threadIdx.x;  // 128
    float4 v0 = src[2 * t];
    float4 v1 = src[2 * t + 1];
    __half2 h[4];
    h[0] = __floats2half2_rn(v0.x, v0.y);
    h[1] = __floats2half2_rn(v0.z, v0.w);
    h[2] = __floats2half2_rn(v1.x, v1.y);
    h[3] = __floats2half2_rn(v1.z, v1.w);
    *(uint4*)(dst + 8 * t) = *(uint4*)h;
}

// ---------------- grouped GEMM: fp16 mma.sync m16n8k16, GBK=64, 3 stages ------
// Templated on TBM (CTA M-tile). TBM=128: exact Round-11/13 proven kernel.
// TBM=64: half-height tiles for GEMM2 to fix its 3.46-wave tail quantization.
#define GBN 128
#define GBK 64
#define GST 3
#define LDH 72                                     // 64 + 8 pad halfs
#define BSZH (GBN * LDH)

template <bool GELU, int TBM, typename OT>
__global__ __launch_bounds__(256, 2)
void gemm_kernel(const __half* __restrict__ A, const __half* __restrict__ Bt,
                 const float* __restrict__ bias, OT* __restrict__ Out,
                 int M, int N, int Kd) {
    constexpr int ASZH = TBM * LDH;
    constexpr int MT = TBM / 32;        // m-tiles per warp (4 or 2)
    constexpr int WMSPAN = TBM / 2;     // rows per wm group (64 or 32)

    int e = blockIdx.z;
    int bm = blockIdx.y, bn = blockIdx.x;
    if (bm * TBM >= g_cnt[e]) return;   // rows never read downstream

    extern __shared__ __half smem[];
    __half* Asm = smem;
    __half* Bsm = smem + GST * ASZH;

    const __half* Ae = A + (size_t)e * M * Kd;
    const __half* Be = Bt + (size_t)e * N * Kd;
    OT* Oe = Out + (size_t)e * M * N;

    int tid = threadIdx.x;
    int warp = tid >> 5, lane = tid & 31;
    int g = lane >> 2, tig = lane & 3;
    int wm = warp >> 2;
    int wn = warp & 3;

    uint32_t sA = (uint32_t)__cvta_generic_to_shared(Asm);
    uint32_t sB = (uint32_t)__cvta_generic_to_shared(Bsm);

    const int nK = Kd / GBK;

    auto issue = [&](int kt, int st) {
        uint32_t aBase = sA + (uint32_t)(st * ASZH) * 2;
        uint32_t bBase = sB + (uint32_t)(st * BSZH) * 2;
#pragma unroll
        for (int i = 0; i < TBM / 32; i++) {      // A: TBM*8 16B chunks
            int ch = tid + 256 * i;
            int r = ch >> 3, c = (ch & 7) * 8;
            cp_async16(aBase + (uint32_t)(r * LDH + c) * 2,
                       Ae + (size_t)(bm * TBM + r) * Kd + kt * GBK + c);
        }
#pragma unroll
        for (int i = 0; i < 4; i++) {             // B: 1024 16B chunks
            int ch = tid + 256 * i;
            int r = ch >> 3, c = (ch & 7) * 8;
            cp_async16(bBase + (uint32_t)(r * LDH + c) * 2,
                       Be + (size_t)(bn * GBN + r) * Kd + kt * GBK + c);
        }
        cp_commit();
    };

#pragma unroll
    for (int s = 0; s < GST - 1; s++) issue(s, s);

    float acc[MT][4][4];
#pragma unroll
    for (int i = 0; i < MT; i++)
#pragma unroll
        for (int j = 0; j < 4; j++)
#pragma unroll
            for (int k = 0; k < 4; k++) acc[i][j][k] = 0.0f;

    for (int kt = 0; kt < nK; kt++) {
        if (kt < nK - 1) cp_wait<GST - 2>(); else cp_wait<0>();
        __syncthreads();

        int nt = kt + GST - 1;
        if (nt < nK) issue(nt, nt % GST);

        const __half* as = Asm + (kt % GST) * ASZH;
        const __half* bs = Bsm + (kt % GST) * BSZH;

#pragma unroll
        for (int kk = 0; kk < 4; kk++) {
            int kb = kk * 16;
            uint32_t af[MT][4];
#pragma unroll
            for (int mt = 0; mt < MT; mt++) {
                int r0 = wm * WMSPAN + mt * 16 + g;
                af[mt][0] = *(const uint32_t*)&as[r0 * LDH + kb + 2 * tig];
                af[mt][1] = *(const uint32_t*)&as[(r0 + 8) * LDH + kb + 2 * tig];
                af[mt][2] = *(const uint32_t*)&as[r0 * LDH + kb + 8 + 2 * tig];
                af[mt][3] = *(const uint32_t*)&as[(r0 + 8) * LDH + kb + 8 + 2 * tig];
            }
            uint32_t bf[4][2];
#pragma unroll
            for (int nt2 = 0; nt2 < 4; nt2++) {
                int c0 = wn * 32 + nt2 * 8 + g;
                bf[nt2][0] = *(const uint32_t*)&bs[c0 * LDH + kb + 2 * tig];
                bf[nt2][1] = *(const uint32_t*)&bs[c0 * LDH + kb + 8 + 2 * tig];
            }
#pragma unroll
            for (int mt = 0; mt < MT; mt++)
#pragma unroll
                for (int nt2 = 0; nt2 < 4; nt2++)
                    mma_f16(acc[mt][nt2], af[mt], bf[nt2]);
        }
    }

    // epilogue
#pragma unroll
    for (int mt = 0; mt < MT; mt++) {
        int r0 = bm * TBM + wm * WMSPAN + mt * 16 + g;
#pragma unroll
        for (int nt2 = 0; nt2 < 4; nt2++) {
            int c0 = bn * GBN + wn * 32 + nt2 * 8 + 2 * tig;
            float bv0 = bias[(size_t)e * N + c0];
            float bv1 = bias[(size_t)e * N + c0 + 1];
            float v00 = acc[mt][nt2][0] + bv0;
            float v01 = acc[mt][nt2][1] + bv1;
            float v10 = acc[mt][nt2][2] + bv0;
            float v11 = acc[mt][nt2][3] + bv1;
            if (GELU) {
                v00 = gelu_tanh(v00); v01 = gelu_tanh(v01);
                v10 = gelu_tanh(v10); v11 = gelu_tanh(v11);
            }
            if constexpr (sizeof(OT) == 2) {
                *(__half2*)((__half*)Oe + (size_t)r0 * N + c0) = __floats2half2_rn(v00, v01);
                *(__half2*)((__half*)Oe + (size_t)(r0 + 8) * N + c0) = __floats2half2_rn(v10, v11);
            } else {
                *(float2*)((float*)Oe + (size_t)r0 * N + c0) = make_float2(v00, v01);
                *(float2*)((float*)Oe + (size_t)(r0 + 8) * N + c0) = make_float2(v10, v11);
            }
        }
    }
}

#define GEMM1_SMEM (GST * (128 * LDH + BSZH) * 2)   // 110592
#define GEMM2_SMEM (GST * (64 * LDH + BSZH) * 2)    // 82944

// ---------------- combine gather (half y inputs) -------------------------------
__global__ void combine_kernel(float* __restrict__ out) {
    int n = blockIdx.x;
    int l0 = g_loc[2 * n], l1 = g_loc[2 * n + 1];
    float w0 = (l0 >= 0) ? g_wf[2 * n] : 0.0f;
    float w1 = (l1 >= 0) ? g_wf[2 * n + 1] : 0.0f;
    const uint4* y0 = (const uint4*)(g_y + (size_t)max(l0, 0) * C_DIM);
    const uint4* y1 = (const uint4*)(g_y + (size_t)max(l1, 0) * C_DIM);
    float4* dst = (float4*)(out + (size_t)n * C_DIM);
    int t = threadIdx.x;  // 128 threads x 8 halfs

    uint4 pa = (l0 >= 0) ? y0[t] : make_uint4(0, 0, 0, 0);
    uint4 pb = (l1 >= 0) ? y1[t] : make_uint4(0, 0, 0, 0);
    const __half2* ha = (const __half2*)&pa;
    const __half2* hb = (const __half2*)&pb;
    float r[8];
#pragma unroll
    for (int j = 0; j < 4; j++) {
        float2 a = __half22float2(ha[j]);
        float2 b = __half22float2(hb[j]);
        r[2 * j]     = w0 * a.x + w1 * b.x;
        r[2 * j + 1] = w0 * a.y + w1 * b.y;
    }
    dst[2 * t]     = make_float4(r[0], r[1], r[2], r[3]);
    dst[2 * t + 1] = make_float4(r[4], r[5], r[6], r[7]);
}

// ---------------- launcher ----------------------------------------------------
extern "C" void kernel_launch(void* const* d_in, const int* in_sizes, int n_in,
                              void* d_out, int out_size) {
    const float* x      = (const float*)d_in[0];
    const float* w_gate = (const float*)d_in[1];
    const float* b_gate = (const float*)d_in[2];
    const float* W1     = (const float*)d_in[3];
    const float* b1     = (const float*)d_in[4];
    const float* W2     = (const float*)d_in[5];
    const float* b2     = (const float*)d_in[6];
    float* out = (float*)d_out;

    cudaFuncSetAttribute((const void*)gemm_kernel<true, 128, __half>,
                         cudaFuncAttributeMaxDynamicSharedMemorySize, GEMM1_SMEM);
    cudaFuncSetAttribute((const void*)gemm_kernel<false, 64, __half>,
                         cudaFuncAttributeMaxDynamicSharedMemorySize, GEMM2_SMEM);

    __half *disp = nullptr, *h = nullptr, *y = nullptr, *w1h = nullptr, *w2h = nullptr;
    cudaGetSymbolAddress((void**)&disp, g_disp);
    cudaGetSymbolAddress((void**)&h, g_h);
    cudaGetSymbolAddress((void**)&y, g_y);
    cudaGetSymbolAddress((void**)&w1h, g_W1h);
    cudaGetSymbolAddress((void**)&w2h, g_W2h);

    init_kernel<<<1, 32>>>();

    // fused: gating (first wave) + both weight transposes in one launch
    prep_kernel<<<1024 + 16384, 256>>>(W1, W2, x, w_gate, b_gate);

    scan_kernel<<<1, 256>>>(out, out_size);
    dispatch_kernel<<<S_SLOTS, 128>>>(x);

    {
        // GEMM1: 128x128 tiles, grid (32,16,8) = 4096 CTAs (13.8 waves, ~1% tail)
        dim3 grid1(F_DIM / GBN, CAP / 128, E_NUM);
        gemm_kernel<true, 128, __half><<<grid1, 256, GEMM1_SMEM>>>(
            disp, w1h, b1, h, CAP, F_DIM, C_DIM);

        // GEMM2: 64x128 tiles, grid (8,32,8) = 2048 CTAs (6.9 waves, ~1% tail)
        dim3 grid2(C_DIM / GBN, CAP / 64, E_NUM);
        gemm_kernel<false, 64, __half><<<grid2, 256, GEMM2_SMEM>>>(
            h, w2h, b2, y, CAP, C_DIM, F_DIM);
    }

    combine_kernel<<<N_TOK, 128>>>(out);
}

// round 15
// speedup vs baseline: 1.1131x; 1.1131x over previous
#include <cuda_runtime.h>
#include <cuda_fp16.h>
#include <cstdint>

// Problem constants
#define N_TOK 8192
#define C_DIM 1024
#define F_DIM 4096
#define E_NUM 8
#define S_SLOTS (N_TOK * 2)
#define CAP 2048

// ---------------- scratch (static device globals) ----------------------------
__device__ __half g_disp[(size_t)E_NUM * CAP * C_DIM];   // 32 MB fp16
__device__ __half g_h[(size_t)E_NUM * CAP * F_DIM];      // 128 MB fp16
__device__ __half g_y[(size_t)E_NUM * CAP * C_DIM];      // 32 MB fp16
__device__ __half g_W1h[(size_t)E_NUM * F_DIM * C_DIM];  // W1^T per expert [F][C] fp16
__device__ __half g_W2h[(size_t)E_NUM * C_DIM * F_DIM];  // W2^T per expert [C][F] fp16
__device__ int    g_eidx[S_SLOTS];
__device__ float  g_wf[S_SLOTS];
__device__ int    g_loc[S_SLOTS];
__device__ int    g_cnt[E_NUM];
__device__ float  g_probs_sum[E_NUM];

// ---------------- helpers ----------------------------------------------------
__device__ __forceinline__ float gelu_tanh(float x) {
    const float k0 = 0.7978845608028654f;
    float x3 = x * x * x;
    float t = tanhf(k0 * (x + 0.044715f * x3));
    return 0.5f * x * (1.0f + t);
}

// fp16 m16n8k16, fp32 accumulate
__device__ __forceinline__ void mma_f16(float* d, const uint32_t* a, const uint32_t* b) {
    asm volatile(
        "mma.sync.aligned.m16n8k16.row.col.f32.f16.f16.f32 "
        "{%0,%1,%2,%3}, {%4,%5,%6,%7}, {%8,%9}, {%0,%1,%2,%3};"
        : "+f"(d[0]), "+f"(d[1]), "+f"(d[2]), "+f"(d[3])
        : "r"(a[0]), "r"(a[1]), "r"(a[2]), "r"(a[3]), "r"(b[0]), "r"(b[1]));
}

__device__ __forceinline__ void cp_async16(uint32_t smem_dst, const void* gmem_src) {
    asm volatile("cp.async.cg.shared.global [%0], [%1], 16;\n" :: "r"(smem_dst), "l"(gmem_src));
}
__device__ __forceinline__ void cp_commit() {
    asm volatile("cp.async.commit_group;\n");
}
template <int N>
__device__ __forceinline__ void cp_wait() {
    asm volatile("cp.async.wait_group %0;\n" :: "n"(N));
}

// ---------------- init -------------------------------------------------------
__global__ void init_kernel() {
    int t = threadIdx.x;
    if (t < E_NUM) g_probs_sum[t] = 0.0f;
}

// ---------------- fused prep: gating first, then W1/W2 transpose-convert -------
__device__ __forceinline__ void transpose_tile(const float* __restrict__ src,
                                               __half* __restrict__ dst,
                                               int K, int N, int bx, int by, int e,
                                               int tid, float* t /* 64x65 */) {
    const float* s = src + (size_t)e * K * N;
    __half* d = dst + (size_t)e * N * K;
    int n0 = bx * 64, k0 = by * 64;

    {
        int r = tid >> 4, c4 = tid & 15;
#pragma unroll
        for (int p = 0; p < 4; p++) {
            float4 v = *(const float4*)(s + (size_t)(k0 + r + p * 16) * N + n0 + c4 * 4);
            float* row = t + (r + p * 16) * 65 + c4 * 4;
            row[0] = v.x; row[1] = v.y; row[2] = v.z; row[3] = v.w;
        }
    }
    __syncthreads();
    {
        int n = tid >> 3, c8 = tid & 7;
#pragma unroll
        for (int p = 0; p < 2; p++) {
            int nn = n + p * 32;
            __half2 h[4];
#pragma unroll
            for (int j = 0; j < 4; j++)
                h[j] = __floats2half2_rn(t[(c8 * 8 + 2 * j) * 65 + nn],
                                         t[(c8 * 8 + 2 * j + 1) * 65 + nn]);
            *(uint4*)(d + (size_t)(n0 + nn) * K + k0 + c8 * 8) = *(uint4*)h;
        }
    }
}

__device__ __forceinline__ void gate_block(const float* __restrict__ x,
                                           const float* __restrict__ w_gate,
                                           const float* __restrict__ b_gate,
                                           int blk, int tid, float* sprob) {
    if (tid < E_NUM) sprob[tid] = 0.0f;
    __syncthreads();

    int warp = tid >> 5, lane = tid & 31;
    int n = blk * 8 + warp;
    const float* xr = x + (size_t)n * C_DIM;

    float acc[E_NUM];
#pragma unroll
    for (int e = 0; e < E_NUM; e++) acc[e] = 0.0f;

    for (int c = lane; c < C_DIM; c += 32) {
        float xv = xr[c];
        const float4* w4 = (const float4*)(w_gate + (size_t)c * E_NUM);
        float4 wa = w4[0], wb = w4[1];
        acc[0] += xv * wa.x; acc[1] += xv * wa.y;
        acc[2] += xv * wa.z; acc[3] += xv * wa.w;
        acc[4] += xv * wb.x; acc[5] += xv * wb.y;
        acc[6] += xv * wb.z; acc[7] += xv * wb.w;
    }
#pragma unroll
    for (int e = 0; e < E_NUM; e++)
#pragma unroll
        for (int o = 16; o > 0; o >>= 1)
            acc[e] += __shfl_down_sync(0xffffffffu, acc[e], o);

    if (lane == 0) {
        float p[E_NUM];
        float mx = -1e30f;
#pragma unroll
        for (int e = 0; e < E_NUM; e++) { p[e] = acc[e] + b_gate[e]; mx = fmaxf(mx, p[e]); }
        float s = 0.0f;
#pragma unroll
        for (int e = 0; e < E_NUM; e++) { p[e] = expf(p[e] - mx); s += p[e]; }
        float inv = 1.0f / s;
#pragma unroll
        for (int e = 0; e < E_NUM; e++) p[e] *= inv;

        int i0 = 0;
#pragma unroll
        for (int e = 1; e < E_NUM; e++) if (p[e] > p[i0]) i0 = e;
        int i1 = (i0 == 0) ? 1 : 0;
#pragma unroll
        for (int e = 0; e < E_NUM; e++) if (e != i0 && p[e] > p[i1]) i1 = e;

        float w0 = p[i0], w1 = p[i1];
        float ws = w0 + w1 + 1e-9f;
        g_eidx[2 * n]     = i0;
        g_eidx[2 * n + 1] = i1;
        g_wf[2 * n]       = w0 / ws;
        g_wf[2 * n + 1]   = w1 / ws;
#pragma unroll
        for (int e = 0; e < E_NUM; e++) atomicAdd(&sprob[e], p[e]);
    }
    __syncthreads();
    if (tid < E_NUM) atomicAdd(&g_probs_sum[tid], sprob[tid]);
}

__global__ void prep_kernel(const float* __restrict__ W1, const float* __restrict__ W2,
                            const float* __restrict__ x,
                            const float* __restrict__ w_gate,
                            const float* __restrict__ b_gate) {
    __shared__ float shbuf[64 * 65];
    int bid = blockIdx.x;
    int tid = threadIdx.x;
    if (bid < 1024) {
        // gate first so it overlaps the transpose waves instead of trailing them
        gate_block(x, w_gate, b_gate, bid, tid, shbuf);
    } else if (bid < 1024 + 8192) {
        int b1 = bid - 1024;
        int e = b1 >> 10;
        int rem = b1 & 1023;
        int bx = rem & 63, by = rem >> 6;
        transpose_tile(W1, g_W1h, C_DIM, F_DIM, bx, by, e, tid, shbuf);
    } else {
        int b2 = bid - 1024 - 8192;
        int e = b2 >> 10;
        int rem = b2 & 1023;
        int bx = rem & 15, by = rem >> 4;
        transpose_tile(W2, g_W2h, F_DIM, C_DIM, bx, by, e, tid, shbuf);
    }
}

// ---------------- FCFS capacity scan + aux loss --------------------------------
__global__ void scan_kernel(float* __restrict__ d_out, int out_size) {
    const int PER = 64;
    int t = threadIdx.x;
    int base = t * PER;

    int cnt[E_NUM];
#pragma unroll
    for (int e = 0; e < E_NUM; e++) cnt[e] = 0;
    for (int i = 0; i < PER; i++) cnt[g_eidx[base + i]]++;

    unsigned long long lo = 0, hi = 0;
#pragma unroll
    for (int e = 0; e < 4; e++) {
        lo |= (unsigned long long)cnt[e] << (16 * e);
        hi |= (unsigned long long)cnt[e + 4] << (16 * e);
    }

    __shared__ unsigned long long s0[256], s1[256];
    s0[t] = lo; s1[t] = hi;
    __syncthreads();
    for (int off = 1; off < 256; off <<= 1) {
        unsigned long long v0 = 0, v1 = 0;
        if (t >= off) { v0 = s0[t - off]; v1 = s1[t - off]; }
        __syncthreads();
        s0[t] += v0; s1[t] += v1;
        __syncthreads();
    }
    unsigned long long p0 = (t > 0) ? s0[t - 1] : 0ULL;
    unsigned long long p1 = (t > 0) ? s1[t - 1] : 0ULL;

    int exc[E_NUM];
#pragma unroll
    for (int e = 0; e < 4; e++) {
        exc[e]     = (int)((p0 >> (16 * e)) & 0xffffULL);
        exc[e + 4] = (int)((p1 >> (16 * e)) & 0xffffULL);
    }
    for (int i = 0; i < PER; i++) {
        int s = base + i;
        int e = g_eidx[s];
        int pos = exc[e]++;
        g_loc[s] = (pos < CAP) ? (e * CAP + pos) : -1;
    }

    if (t == 0) {
        unsigned long long t0 = s0[255], t1 = s1[255];
        float sumload = 0.0f, load[E_NUM];
#pragma unroll
        for (int e = 0; e < 4; e++) {
            int c0 = (int)((t0 >> (16 * e)) & 0xffffULL);
            int c1 = (int)((t1 >> (16 * e)) & 0xffffULL);
            g_cnt[e]     = min(c0, CAP);
            g_cnt[e + 4] = min(c1, CAP);
            load[e]     = (float)min(c0, CAP);
            load[e + 4] = (float)min(c1, CAP);
        }
#pragma unroll
        for (int e = 0; e < E_NUM; e++) sumload += load[e];
        float fe[E_NUM], sfe = 0.0f;
#pragma unroll
        for (int e = 0; e < E_NUM; e++) { fe[e] = g_probs_sum[e] / (float)N_TOK; sfe += fe[e]; }
        float aux = 0.0f;
#pragma unroll
        for (int e = 0; e < E_NUM; e++) {
            float fn = fe[e] / (sfe + 1e-9f);
            float fa = load[e] / (sumload + 1e-9f);
            float d = fn - fa;
            aux += d * d;
        }
        aux = 0.01f * aux / (float)E_NUM;
        if (out_size > N_TOK * C_DIM)
            d_out[(size_t)N_TOK * C_DIM] = aux;
    }
}

// ---------------- dispatch gather (fp16 convert at write) ----------------------
__global__ void dispatch_kernel(const float* __restrict__ x) {
    int s = blockIdx.x;
    int loc = g_loc[s];
    if (loc < 0) return;
    const float4* src = (const float4*)(x + ((size_t)(s >> 1)) * C_DIM);
    __half* dst = g_disp + (size_t)loc * C_DIM;
    int t = threadIdx.x;  // 128
    float4 v0 = src[2 * t];
    float4 v1 = src[2 * t + 1];
    __half2 h[4];
    h[0] = __floats2half2_rn(v0.x, v0.y);
    h[1] = __floats2half2_rn(v0.z, v0.w);
    h[2] = __floats2half2_rn(v1.x, v1.y);
    h[3] = __floats2half2_rn(v1.z, v1.w);
    *(uint4*)(dst + 8 * t) = *(uint4*)h;
}

// ---------------- grouped GEMM: fp16 mma.sync m16n8k16, GBK=64, 3 stages ------
// Round-11/13 proven configuration: 128x128 tile, 2 CTAs/SM, single barrier/iter.
#define GBM 128
#define GBN 128
#define GBK 64
#define GST 3
#define LDH 72                                     // 64 + 8 pad halfs
#define ASZH (GBM * LDH)                           // 9216 halfs
#define BSZH (GBN * LDH)
#define STG_BYTES ((ASZH + BSZH) * 2)              // 36864
#define GEMM_SMEM_BYTES (GST * STG_BYTES)          // 110592

template <bool GELU, typename OT>
__global__ __launch_bounds__(256, 2)
void gemm_kernel(const __half* __restrict__ A, const __half* __restrict__ Bt,
                 const float* __restrict__ bias, OT* __restrict__ Out,
                 int M, int N, int Kd) {
    int e = blockIdx.z;
    int bm = blockIdx.y, bn = blockIdx.x;
    if (bm * GBM >= g_cnt[e]) return;   // rows never read downstream

    extern __shared__ __half smem[];
    __half* Asm = smem;
    __half* Bsm = smem + GST * ASZH;

    const __half* Ae = A + (size_t)e * M * Kd;
    const __half* Be = Bt + (size_t)e * N * Kd;
    OT* Oe = Out + (size_t)e * M * N;

    int tid = threadIdx.x;
    int warp = tid >> 5, lane = tid & 31;
    int g = lane >> 2, tig = lane & 3;
    int wm = warp >> 2;
    int wn = warp & 3;

    uint32_t sA = (uint32_t)__cvta_generic_to_shared(Asm);
    uint32_t sB = (uint32_t)__cvta_generic_to_shared(Bsm);

    const int nK = Kd / GBK;

    // one K-tile: A 128x64 halfs = 1024 16B chunks, B same
    auto issue = [&](int kt, int st) {
        uint32_t aBase = sA + (uint32_t)(st * ASZH) * 2;
        uint32_t bBase = sB + (uint32_t)(st * BSZH) * 2;
#pragma unroll
        for (int i = 0; i < 4; i++) {
            int ch = tid + 256 * i;
            int r = ch >> 3, c = (ch & 7) * 8;
            cp_async16(aBase + (uint32_t)(r * LDH + c) * 2,
                       Ae + (size_t)(bm * GBM + r) * Kd + kt * GBK + c);
        }
#pragma unroll
        for (int i = 0; i < 4; i++) {
            int ch = tid + 256 * i;
            int r = ch >> 3, c = (ch & 7) * 8;
            cp_async16(bBase + (uint32_t)(r * LDH + c) * 2,
                       Be + (size_t)(bn * GBN + r) * Kd + kt * GBK + c);
        }
        cp_commit();
    };

    // prologue: fill stages 0..GST-2
#pragma unroll
    for (int s = 0; s < GST - 1; s++) issue(s, s);

    float acc[4][4][4];
#pragma unroll
    for (int i = 0; i < 4; i++)
#pragma unroll
        for (int j = 0; j < 4; j++)
#pragma unroll
            for (int k = 0; k < 4; k++) acc[i][j][k] = 0.0f;

    for (int kt = 0; kt < nK; kt++) {
        if (kt < nK - 1) cp_wait<GST - 2>(); else cp_wait<0>();
        __syncthreads();

        int nt = kt + GST - 1;
        if (nt < nK) issue(nt, nt % GST);

        const __half* as = Asm + (kt % GST) * ASZH;
        const __half* bs = Bsm + (kt % GST) * BSZH;

#pragma unroll
        for (int kk = 0; kk < 4; kk++) {
            int kb = kk * 16;
            uint32_t af[4][4];
#pragma unroll
            for (int mt = 0; mt < 4; mt++) {
                int r0 = wm * 64 + mt * 16 + g;
                af[mt][0] = *(const uint32_t*)&as[r0 * LDH + kb + 2 * tig];
                af[mt][1] = *(const uint32_t*)&as[(r0 + 8) * LDH + kb + 2 * tig];
                af[mt][2] = *(const uint32_t*)&as[r0 * LDH + kb + 8 + 2 * tig];
                af[mt][3] = *(const uint32_t*)&as[(r0 + 8) * LDH + kb + 8 + 2 * tig];
            }
            uint32_t bf[4][2];
#pragma unroll
            for (int nt2 = 0; nt2 < 4; nt2++) {
                int c0 = wn * 32 + nt2 * 8 + g;
                bf[nt2][0] = *(const uint32_t*)&bs[c0 * LDH + kb + 2 * tig];
                bf[nt2][1] = *(const uint32_t*)&bs[c0 * LDH + kb + 8 + 2 * tig];
            }
#pragma unroll
            for (int mt = 0; mt < 4; mt++)
#pragma unroll
                for (int nt2 = 0; nt2 < 4; nt2++)
                    mma_f16(acc[mt][nt2], af[mt], bf[nt2]);
        }
    }

    // epilogue
#pragma unroll
    for (int mt = 0; mt < 4; mt++) {
        int r0 = bm * GBM + wm * 64 + mt * 16 + g;
#pragma unroll
        for (int nt2 = 0; nt2 < 4; nt2++) {
            int c0 = bn * GBN + wn * 32 + nt2 * 8 + 2 * tig;
            float bv0 = bias[(size_t)e * N + c0];
            float bv1 = bias[(size_t)e * N + c0 + 1];
            float v00 = acc[mt][nt2][0] + bv0;
            float v01 = acc[mt][nt2][1] + bv1;
            float v10 = acc[mt][nt2][2] + bv0;
            float v11 = acc[mt][nt2][3] + bv1;
            if (GELU) {
                v00 = gelu_tanh(v00); v01 = gelu_tanh(v01);
                v10 = gelu_tanh(v10); v11 = gelu_tanh(v11);
            }
            if constexpr (sizeof(OT) == 2) {
                *(__half2*)((__half*)Oe + (size_t)r0 * N + c0) = __floats2half2_rn(v00, v01);
                *(__half2*)((__half*)Oe + (size_t)(r0 + 8) * N + c0) = __floats2half2_rn(v10, v11);
            } else {
                *(float2*)((float*)Oe + (size_t)r0 * N + c0) = make_float2(v00, v01);
                *(float2*)((float*)Oe + (size_t)(r0 + 8) * N + c0) = make_float2(v10, v11);
            }
        }
    }
}

// ---------------- combine gather (half y inputs) -------------------------------
__global__ void combine_kernel(float* __restrict__ out) {
    int n = blockIdx.x;
    int l0 = g_loc[2 * n], l1 = g_loc[2 * n + 1];
    float w0 = (l0 >= 0) ? g_wf[2 * n] : 0.0f;
    float w1 = (l1 >= 0) ? g_wf[2 * n + 1] : 0.0f;
    const uint4* y0 = (const uint4*)(g_y + (size_t)max(l0, 0) * C_DIM);
    const uint4* y1 = (const uint4*)(g_y + (size_t)max(l1, 0) * C_DIM);
    float4* dst = (float4*)(out + (size_t)n * C_DIM);
    int t = threadIdx.x;  // 128 threads x 8 halfs

    uint4 pa = (l0 >= 0) ? y0[t] : make_uint4(0, 0, 0, 0);
    uint4 pb = (l1 >= 0) ? y1[t] : make_uint4(0, 0, 0, 0);
    const __half2* ha = (const __half2*)&pa;
    const __half2* hb = (const __half2*)&pb;
    float r[8];
#pragma unroll
    for (int j = 0; j < 4; j++) {
        float2 a = __half22float2(ha[j]);
        float2 b = __half22float2(hb[j]);
        r[2 * j]     = w0 * a.x + w1 * b.x;
        r[2 * j + 1] = w0 * a.y + w1 * b.y;
    }
    dst[2 * t]     = make_float4(r[0], r[1], r[2], r[3]);
    dst[2 * t + 1] = make_float4(r[4], r[5], r[6], r[7]);
}

// ---------------- launcher ----------------------------------------------------
extern "C" void kernel_launch(void* const* d_in, const int* in_sizes, int n_in,
                              void* d_out, int out_size) {
    const float* x      = (const float*)d_in[0];
    const float* w_gate = (const float*)d_in[1];
    const float* b_gate = (const float*)d_in[2];
    const float* W1     = (const float*)d_in[3];
    const float* b1     = (const float*)d_in[4];
    const float* W2     = (const float*)d_in[5];
    const float* b2     = (const float*)d_in[6];
    float* out = (float*)d_out;

    cudaFuncSetAttribute((const void*)gemm_kernel<true, __half>,
                         cudaFuncAttributeMaxDynamicSharedMemorySize, GEMM_SMEM_BYTES);
    cudaFuncSetAttribute((const void*)gemm_kernel<false, __half>,
                         cudaFuncAttributeMaxDynamicSharedMemorySize, GEMM_SMEM_BYTES);

    __half *disp = nullptr, *h = nullptr, *y = nullptr, *w1h = nullptr, *w2h = nullptr;
    cudaGetSymbolAddress((void**)&disp, g_disp);
    cudaGetSymbolAddress((void**)&h, g_h);
    cudaGetSymbolAddress((void**)&y, g_y);
    cudaGetSymbolAddress((void**)&w1h, g_W1h);
    cudaGetSymbolAddress((void**)&w2h, g_W2h);

    init_kernel<<<1, 32>>>();

    // fused: gating (first wave) + both weight transposes in one launch
    prep_kernel<<<1024 + 16384, 256>>>(W1, W2, x, w_gate, b_gate);

    scan_kernel<<<1, 256>>>(out, out_size);
    dispatch_kernel<<<S_SLOTS, 128>>>(x);

    {
        dim3 grid1(F_DIM / GBN, CAP / GBM, E_NUM);
        gemm_kernel<true, __half><<<grid1, 256, GEMM_SMEM_BYTES>>>(
            disp, w1h, b1, h, CAP, F_DIM, C_DIM);

        dim3 grid2(C_DIM / GBN, CAP / GBM, E_NUM);
        gemm_kernel<false, __half><<<grid2, 256, GEMM_SMEM_BYTES>>>(
            h, w2h, b2, y, CAP, C_DIM, F_DIM);
    }

    combine_kernel<<<N_TOK, 128>>>(out);
}

// round 16
// speedup vs baseline: 1.1142x; 1.0010x over previous
#include <cuda_runtime.h>
#include <cuda_fp16.h>
#include <cstdint>

// Problem constants
#define N_TOK 8192
#define C_DIM 1024
#define F_DIM 4096
#define E_NUM 8
#define S_SLOTS (N_TOK * 2)
#define CAP 2048

// ---------------- scratch (static device globals) ----------------------------
__device__ __half g_disp[(size_t)E_NUM * CAP * C_DIM];   // 32 MB fp16
__device__ __half g_h[(size_t)E_NUM * CAP * F_DIM];      // 128 MB fp16
__device__ __half g_y[(size_t)E_NUM * CAP * C_DIM];      // 32 MB fp16
__device__ __half g_W1h[(size_t)E_NUM * F_DIM * C_DIM];  // W1^T per expert [F][C] fp16
__device__ __half g_W2h[(size_t)E_NUM * C_DIM * F_DIM];  // W2^T per expert [C][F] fp16
__device__ int    g_eidx[S_SLOTS];
__device__ float  g_wf[S_SLOTS];
__device__ int    g_loc[S_SLOTS];
__device__ int    g_cnt[E_NUM];
__device__ float  g_probs_sum[E_NUM];

// ---------------- helpers ----------------------------------------------------
__device__ __forceinline__ float gelu_tanh(float x) {
    const float k0 = 0.7978845608028654f;
    float x3 = x * x * x;
    float t = tanhf(k0 * (x + 0.044715f * x3));
    return 0.5f * x * (1.0f + t);
}

// fp16 m16n8k16, fp32 accumulate
__device__ __forceinline__ void mma_f16(float* d, const uint32_t* a, const uint32_t* b) {
    asm volatile(
        "mma.sync.aligned.m16n8k16.row.col.f32.f16.f16.f32 "
        "{%0,%1,%2,%3}, {%4,%5,%6,%7}, {%8,%9}, {%0,%1,%2,%3};"
        : "+f"(d[0]), "+f"(d[1]), "+f"(d[2]), "+f"(d[3])
        : "r"(a[0]), "r"(a[1]), "r"(a[2]), "r"(a[3]), "r"(b[0]), "r"(b[1]));
}

__device__ __forceinline__ void cp_async16(uint32_t smem_dst, const void* gmem_src) {
    asm volatile("cp.async.cg.shared.global [%0], [%1], 16;\n" :: "r"(smem_dst), "l"(gmem_src));
}
__device__ __forceinline__ void cp_commit() {
    asm volatile("cp.async.commit_group;\n");
}
template <int N>
__device__ __forceinline__ void cp_wait() {
    asm volatile("cp.async.wait_group %0;\n" :: "n"(N));
}

// ---------------- init -------------------------------------------------------
__global__ void init_kernel() {
    int t = threadIdx.x;
    if (t < E_NUM) g_probs_sum[t] = 0.0f;
}

// ---------------- weight transpose + fp16 convert: [E][K][N] -> [E][N][K] -----
__global__ void transpose_h_kernel(const float* __restrict__ src,
                                   __half* __restrict__ dst, int K, int N) {
    __shared__ float t[64][65];
    int e = blockIdx.z;
    const float* s = src + (size_t)e * K * N;
    __half* d = dst + (size_t)e * N * K;
    int n0 = blockIdx.x * 64, k0 = blockIdx.y * 64;
    int tid = threadIdx.x;

    {
        int r = tid >> 4, c4 = tid & 15;
#pragma unroll
        for (int p = 0; p < 4; p++) {
            float4 v = *(const float4*)(s + (size_t)(k0 + r + p * 16) * N + n0 + c4 * 4);
            t[r + p * 16][c4 * 4 + 0] = v.x;
            t[r + p * 16][c4 * 4 + 1] = v.y;
            t[r + p * 16][c4 * 4 + 2] = v.z;
            t[r + p * 16][c4 * 4 + 3] = v.w;
        }
    }
    __syncthreads();
    {
        int n = tid >> 3, c8 = tid & 7;
#pragma unroll
        for (int p = 0; p < 2; p++) {
            int nn = n + p * 32;
            __half2 h[4];
#pragma unroll
            for (int j = 0; j < 4; j++)
                h[j] = __floats2half2_rn(t[c8 * 8 + 2 * j][nn], t[c8 * 8 + 2 * j + 1][nn]);
            *(uint4*)(d + (size_t)(n0 + nn) * K + k0 + c8 * 8) = *(uint4*)h;
        }
    }
}

// ---------------- gating (scalar x loads, proven 35us version) -----------------
__global__ void gate_kernel(const float* __restrict__ x,
                            const float* __restrict__ w_gate,
                            const float* __restrict__ b_gate) {
    __shared__ float sprob[E_NUM];
    int tid = threadIdx.x;
    if (tid < E_NUM) sprob[tid] = 0.0f;
    __syncthreads();

    int warp = tid >> 5, lane = tid & 31;
    int n = blockIdx.x * 8 + warp;
    const float* xr = x + (size_t)n * C_DIM;

    float acc[E_NUM];
#pragma unroll
    for (int e = 0; e < E_NUM; e++) acc[e] = 0.0f;

    for (int c = lane; c < C_DIM; c += 32) {
        float xv = xr[c];
        const float4* w4 = (const float4*)(w_gate + (size_t)c * E_NUM);
        float4 wa = w4[0], wb = w4[1];
        acc[0] += xv * wa.x; acc[1] += xv * wa.y;
        acc[2] += xv * wa.z; acc[3] += xv * wa.w;
        acc[4] += xv * wb.x; acc[5] += xv * wb.y;
        acc[6] += xv * wb.z; acc[7] += xv * wb.w;
    }
#pragma unroll
    for (int e = 0; e < E_NUM; e++)
#pragma unroll
        for (int o = 16; o > 0; o >>= 1)
            acc[e] += __shfl_down_sync(0xffffffffu, acc[e], o);

    if (lane == 0) {
        float p[E_NUM];
        float mx = -1e30f;
#pragma unroll
        for (int e = 0; e < E_NUM; e++) { p[e] = acc[e] + b_gate[e]; mx = fmaxf(mx, p[e]); }
        float s = 0.0f;
#pragma unroll
        for (int e = 0; e < E_NUM; e++) { p[e] = expf(p[e] - mx); s += p[e]; }
        float inv = 1.0f / s;
#pragma unroll
        for (int e = 0; e < E_NUM; e++) p[e] *= inv;

        int i0 = 0;
#pragma unroll
        for (int e = 1; e < E_NUM; e++) if (p[e] > p[i0]) i0 = e;
        int i1 = (i0 == 0) ? 1 : 0;
#pragma unroll
        for (int e = 0; e < E_NUM; e++) if (e != i0 && p[e] > p[i1]) i1 = e;

        float w0 = p[i0], w1 = p[i1];
        float ws = w0 + w1 + 1e-9f;
        g_eidx[2 * n]     = i0;
        g_eidx[2 * n + 1] = i1;
        g_wf[2 * n]       = w0 / ws;
        g_wf[2 * n + 1]   = w1 / ws;
#pragma unroll
        for (int e = 0; e < E_NUM; e++) atomicAdd(&sprob[e], p[e]);
    }
    __syncthreads();
    if (tid < E_NUM) atomicAdd(&g_probs_sum[tid], sprob[tid]);
}

// ---------------- FCFS capacity scan + aux loss --------------------------------
__global__ void scan_kernel(float* __restrict__ d_out, int out_size) {
    const int PER = 64;
    int t = threadIdx.x;
    int base = t * PER;

    int cnt[E_NUM];
#pragma unroll
    for (int e = 0; e < E_NUM; e++) cnt[e] = 0;
    for (int i = 0; i < PER; i++) cnt[g_eidx[base + i]]++;

    unsigned long long lo = 0, hi = 0;
#pragma unroll
    for (int e = 0; e < 4; e++) {
        lo |= (unsigned long long)cnt[e] << (16 * e);
        hi |= (unsigned long long)cnt[e + 4] << (16 * e);
    }

    __shared__ unsigned long long s0[256], s1[256];
    s0[t] = lo; s1[t] = hi;
    __syncthreads();
    for (int off = 1; off < 256; off <<= 1) {
        unsigned long long v0 = 0, v1 = 0;
        if (t >= off) { v0 = s0[t - off]; v1 = s1[t - off]; }
        __syncthreads();
        s0[t] += v0; s1[t] += v1;
        __syncthreads();
    }
    unsigned long long p0 = (t > 0) ? s0[t - 1] : 0ULL;
    unsigned long long p1 = (t > 0) ? s1[t - 1] : 0ULL;

    int exc[E_NUM];
#pragma unroll
    for (int e = 0; e < 4; e++) {
        exc[e]     = (int)((p0 >> (16 * e)) & 0xffffULL);
        exc[e + 4] = (int)((p1 >> (16 * e)) & 0xffffULL);
    }
    for (int i = 0; i < PER; i++) {
        int s = base + i;
        int e = g_eidx[s];
        int pos = exc[e]++;
        g_loc[s] = (pos < CAP) ? (e * CAP + pos) : -1;
    }

    if (t == 0) {
        unsigned long long t0 = s0[255], t1 = s1[255];
        float sumload = 0.0f, load[E_NUM];
#pragma unroll
        for (int e = 0; e < 4; e++) {
            int c0 = (int)((t0 >> (16 * e)) & 0xffffULL);
            int c1 = (int)((t1 >> (16 * e)) & 0xffffULL);
            g_cnt[e]     = min(c0, CAP);
            g_cnt[e + 4] = min(c1, CAP);
            load[e]     = (float)min(c0, CAP);
            load[e + 4] = (float)min(c1, CAP);
        }
#pragma unroll
        for (int e = 0; e < E_NUM; e++) sumload += load[e];
        float fe[E_NUM], sfe = 0.0f;
#pragma unroll
        for (int e = 0; e < E_NUM; e++) { fe[e] = g_probs_sum[e] / (float)N_TOK; sfe += fe[e]; }
        float aux = 0.0f;
#pragma unroll
        for (int e = 0; e < E_NUM; e++) {
            float fn = fe[e] / (sfe + 1e-9f);
            float fa = load[e] / (sumload + 1e-9f);
            float d = fn - fa;
            aux += d * d;
        }
        aux = 0.01f * aux / (float)E_NUM;
        if (out_size > N_TOK * C_DIM)
            d_out[(size_t)N_TOK * C_DIM] = aux;
    }
}

// ---------------- dispatch gather (fp16 convert at write) ----------------------
__global__ void dispatch_kernel(const float* __restrict__ x) {
    int s = blockIdx.x;
    int loc = g_loc[s];
    if (loc < 0) return;
    const float4* src = (const float4*)(x + ((size_t)(s >> 1)) * C_DIM);
    __half* dst = g_disp + (size_t)loc * C_DIM;
    int t = threadIdx.x;  // 128
    float4 v0 = src[2 * t];
    float4 v1 = src[2 * t + 1];
    __half2 h[4];
    h[0] = __floats2half2_rn(v0.x, v0.y);
    h[1] = __floats2half2_rn(v0.z, v0.w);
    h[2] = __floats2half2_rn(v1.x, v1.y);
    h[3] = __floats2half2_rn(v1.z, v1.w);
    *(uint4*)(dst + 8 * t) = *(uint4*)h;
}

// ---------------- grouped GEMM: fp16 mma.sync m16n8k16, GBK=64, 3 stages ------
// Round-11/13 proven configuration: 128x128 tile, 2 CTAs/SM, single barrier/iter.
#define GBM 128
#define GBN 128
#define GBK 64
#define GST 3
#define LDH 72                                     // 64 + 8 pad halfs
#define ASZH (GBM * LDH)                           // 9216 halfs
#define BSZH (GBN * LDH)
#define STG_BYTES ((ASZH + BSZH) * 2)              // 36864
#define GEMM_SMEM_BYTES (GST * STG_BYTES)          // 110592

template <bool GELU, typename OT>
__global__ __launch_bounds__(256, 2)
void gemm_kernel(const __half* __restrict__ A, const __half* __restrict__ Bt,
                 const float* __restrict__ bias, OT* __restrict__ Out,
                 int M, int N, int Kd) {
    int e = blockIdx.z;
    int bm = blockIdx.y, bn = blockIdx.x;
    if (bm * GBM >= g_cnt[e]) return;   // rows never read downstream

    extern __shared__ __half smem[];
    __half* Asm = smem;
    __half* Bsm = smem + GST * ASZH;

    const __half* Ae = A + (size_t)e * M * Kd;
    const __half* Be = Bt + (size_t)e * N * Kd;
    OT* Oe = Out + (size_t)e * M * N;

    int tid = threadIdx.x;
    int warp = tid >> 5, lane = tid & 31;
    int g = lane >> 2, tig = lane & 3;
    int wm = warp >> 2;
    int wn = warp & 3;

    uint32_t sA = (uint32_t)__cvta_generic_to_shared(Asm);
    uint32_t sB = (uint32_t)__cvta_generic_to_shared(Bsm);

    const int nK = Kd / GBK;

    auto issue = [&](int kt, int st) {
        uint32_t aBase = sA + (uint32_t)(st * ASZH) * 2;
        uint32_t bBase = sB + (uint32_t)(st * BSZH) * 2;
#pragma unroll
        for (int i = 0; i < 4; i++) {
            int ch = tid + 256 * i;
            int r = ch >> 3, c = (ch & 7) * 8;
            cp_async16(aBase + (uint32_t)(r * LDH + c) * 2,
                       Ae + (size_t)(bm * GBM + r) * Kd + kt * GBK + c);
        }
#pragma unroll
        for (int i = 0; i < 4; i++) {
            int ch = tid + 256 * i;
            int r = ch >> 3, c = (ch & 7) * 8;
            cp_async16(bBase + (uint32_t)(r * LDH + c) * 2,
                       Be + (size_t)(bn * GBN + r) * Kd + kt * GBK + c);
        }
        cp_commit();
    };

#pragma unroll
    for (int s = 0; s < GST - 1; s++) issue(s, s);

    float acc[4][4][4];
#pragma unroll
    for (int i = 0; i < 4; i++)
#pragma unroll
        for (int j = 0; j < 4; j++)
#pragma unroll
            for (int k = 0; k < 4; k++) acc[i][j][k] = 0.0f;

    for (int kt = 0; kt < nK; kt++) {
        if (kt < nK - 1) cp_wait<GST - 2>(); else cp_wait<0>();
        __syncthreads();

        int nt = kt + GST - 1;
        if (nt < nK) issue(nt, nt % GST);

        const __half* as = Asm + (kt % GST) * ASZH;
        const __half* bs = Bsm + (kt % GST) * BSZH;

#pragma unroll
        for (int kk = 0; kk < 4; kk++) {
            int kb = kk * 16;
            uint32_t af[4][4];
#pragma unroll
            for (int mt = 0; mt < 4; mt++) {
                int r0 = wm * 64 + mt * 16 + g;
                af[mt][0] = *(const uint32_t*)&as[r0 * LDH + kb + 2 * tig];
                af[mt][1] = *(const uint32_t*)&as[(r0 + 8) * LDH + kb + 2 * tig];
                af[mt][2] = *(const uint32_t*)&as[r0 * LDH + kb + 8 + 2 * tig];
                af[mt][3] = *(const uint32_t*)&as[(r0 + 8) * LDH + kb + 8 + 2 * tig];
            }
            uint32_t bf[4][2];
#pragma unroll
            for (int nt2 = 0; nt2 < 4; nt2++) {
                int c0 = wn * 32 + nt2 * 8 + g;
                bf[nt2][0] = *(const uint32_t*)&bs[c0 * LDH + kb + 2 * tig];
                bf[nt2][1] = *(const uint32_t*)&bs[c0 * LDH + kb + 8 + 2 * tig];
            }
#pragma unroll
            for (int mt = 0; mt < 4; mt++)
#pragma unroll
                for (int nt2 = 0; nt2 < 4; nt2++)
                    mma_f16(acc[mt][nt2], af[mt], bf[nt2]);
        }
    }

    // epilogue
#pragma unroll
    for (int mt = 0; mt < 4; mt++) {
        int r0 = bm * GBM + wm * 64 + mt * 16 + g;
#pragma unroll
        for (int nt2 = 0; nt2 < 4; nt2++) {
            int c0 = bn * GBN + wn * 32 + nt2 * 8 + 2 * tig;
            float bv0 = bias[(size_t)e * N + c0];
            float bv1 = bias[(size_t)e * N + c0 + 1];
            float v00 = acc[mt][nt2][0] + bv0;
            float v01 = acc[mt][nt2][1] + bv1;
            float v10 = acc[mt][nt2][2] + bv0;
            float v11 = acc[mt][nt2][3] + bv1;
            if (GELU) {
                v00 = gelu_tanh(v00); v01 = gelu_tanh(v01);
                v10 = gelu_tanh(v10); v11 = gelu_tanh(v11);
            }
            if constexpr (sizeof(OT) == 2) {
                *(__half2*)((__half*)Oe + (size_t)r0 * N + c0) = __floats2half2_rn(v00, v01);
                *(__half2*)((__half*)Oe + (size_t)(r0 + 8) * N + c0) = __floats2half2_rn(v10, v11);
            } else {
                *(float2*)((float*)Oe + (size_t)r0 * N + c0) = make_float2(v00, v01);
                *(float2*)((float*)Oe + (size_t)(r0 + 8) * N + c0) = make_float2(v10, v11);
            }
        }
    }
}

// ---------------- combine gather (half y inputs) -------------------------------
__global__ void combine_kernel(float* __restrict__ out) {
    int n = blockIdx.x;
    int l0 = g_loc[2 * n], l1 = g_loc[2 * n + 1];
    float w0 = (l0 >= 0) ? g_wf[2 * n] : 0.0f;
    float w1 = (l1 >= 0) ? g_wf[2 * n + 1] : 0.0f;
    const uint4* y0 = (const uint4*)(g_y + (size_t)max(l0, 0) * C_DIM);
    const uint4* y1 = (const uint4*)(g_y + (size_t)max(l1, 0) * C_DIM);
    float4* dst = (float4*)(out + (size_t)n * C_DIM);
    int t = threadIdx.x;  // 128 threads x 8 halfs

    uint4 pa = (l0 >= 0) ? y0[t] : make_uint4(0, 0, 0, 0);
    uint4 pb = (l1 >= 0) ? y1[t] : make_uint4(0, 0, 0, 0);
    const __half2* ha = (const __half2*)&pa;
    const __half2* hb = (const __half2*)&pb;
    float r[8];
#pragma unroll
    for (int j = 0; j < 4; j++) {
        float2 a = __half22float2(ha[j]);
        float2 b = __half22float2(hb[j]);
        r[2 * j]     = w0 * a.x + w1 * b.x;
        r[2 * j + 1] = w0 * a.y + w1 * b.y;
    }
    dst[2 * t]     = make_float4(r[0], r[1], r[2], r[3]);
    dst[2 * t + 1] = make_float4(r[4], r[5], r[6], r[7]);
}

// ---------------- launcher ----------------------------------------------------
extern "C" void kernel_launch(void* const* d_in, const int* in_sizes, int n_in,
                              void* d_out, int out_size) {
    const float* x      = (const float*)d_in[0];
    const float* w_gate = (const float*)d_in[1];
    const float* b_gate = (const float*)d_in[2];
    const float* W1     = (const float*)d_in[3];
    const float* b1     = (const float*)d_in[4];
    const float* W2     = (const float*)d_in[5];
    const float* b2     = (const float*)d_in[6];
    float* out = (float*)d_out;

    cudaFuncSetAttribute((const void*)gemm_kernel<true, __half>,
                         cudaFuncAttributeMaxDynamicSharedMemorySize, GEMM_SMEM_BYTES);
    cudaFuncSetAttribute((const void*)gemm_kernel<false, __half>,
                         cudaFuncAttributeMaxDynamicSharedMemorySize, GEMM_SMEM_BYTES);

    __half *disp = nullptr, *h = nullptr, *y = nullptr, *w1h = nullptr, *w2h = nullptr;
    cudaGetSymbolAddress((void**)&disp, g_disp);
    cudaGetSymbolAddress((void**)&h, g_h);
    cudaGetSymbolAddress((void**)&y, g_y);
    cudaGetSymbolAddress((void**)&w1h, g_W1h);
    cudaGetSymbolAddress((void**)&w2h, g_W2h);

    // fork a side stream for the weight transposes (independent of routing chain)
    cudaStream_t s2;
    cudaStreamCreateWithFlags(&s2, cudaStreamNonBlocking);
    cudaEvent_t evFork, evW1, evW2;
    cudaEventCreateWithFlags(&evFork, cudaEventDisableTiming);
    cudaEventCreateWithFlags(&evW1, cudaEventDisableTiming);
    cudaEventCreateWithFlags(&evW2, cudaEventDisableTiming);

    init_kernel<<<1, 32>>>();
    cudaEventRecord(evFork, 0);
    cudaStreamWaitEvent(s2, evFork, 0);

    // branch B (s2): W1 transpose (needed by GEMM1), then W2 (needed by GEMM2)
    {
        dim3 blk(256);
        dim3 t1(F_DIM / 64, C_DIM / 64, E_NUM);
        transpose_h_kernel<<<t1, blk, 0, s2>>>(W1, w1h, C_DIM, F_DIM);
        cudaEventRecord(evW1, s2);
        dim3 t2(C_DIM / 64, F_DIM / 64, E_NUM);
        transpose_h_kernel<<<t2, blk, 0, s2>>>(W2, w2h, F_DIM, C_DIM);
        cudaEventRecord(evW2, s2);
    }

    // branch A (main): gate -> scan -> dispatch
    gate_kernel<<<N_TOK / 8, 256>>>(x, w_gate, b_gate);
    scan_kernel<<<1, 256>>>(out, out_size);
    dispatch_kernel<<<S_SLOTS, 128>>>(x);

    // join W1 before GEMM1; W2 transpose overlaps GEMM1 and joins before GEMM2
    cudaStreamWaitEvent(0, evW1, 0);
    {
        dim3 grid1(F_DIM / GBN, CAP / GBM, E_NUM);
        gemm_kernel<true, __half><<<grid1, 256, GEMM_SMEM_BYTES>>>(
            disp, w1h, b1, h, CAP, F_DIM, C_DIM);
    }
    cudaStreamWaitEvent(0, evW2, 0);
    {
        dim3 grid2(C_DIM / GBN, CAP / GBM, E_NUM);
        gemm_kernel<false, __half><<<grid2, 256, GEMM_SMEM_BYTES>>>(
            h, w2h, b2, y, CAP, C_DIM, F_DIM);
    }

    combine_kernel<<<N_TOK, 128>>>(out);

    // host-side handles; safe to release after enqueue (graph retains topology)
    cudaEventDestroy(evFork);
    cudaEventDestroy(evW1);
    cudaEventDestroy(evW2);
    cudaStreamDestroy(s2);
}

// round 17
// speedup vs baseline: 1.1231x; 1.0080x over previous
#include <cuda_runtime.h>
#include <cuda_fp16.h>
#include <cstdint>

// Problem constants
#define N_TOK 8192
#define C_DIM 1024
#define F_DIM 4096
#define E_NUM 8
#define S_SLOTS (N_TOK * 2)
#define CAP 2048

// ---------------- scratch (static device globals) ----------------------------
__device__ __half g_disp[(size_t)E_NUM * CAP * C_DIM];   // 32 MB fp16
__device__ __half g_h[(size_t)E_NUM * CAP * F_DIM];      // 128 MB fp16
__device__ __half g_y[(size_t)E_NUM * CAP * C_DIM];      // 32 MB fp16
__device__ __half g_W1h[(size_t)E_NUM * F_DIM * C_DIM];  // W1^T per expert [F][C] fp16
__device__ __half g_W2h[(size_t)E_NUM * C_DIM * F_DIM];  // W2^T per expert [C][F] fp16
__device__ int    g_eidx[S_SLOTS];
__device__ float  g_wf[S_SLOTS];
__device__ int    g_loc[S_SLOTS];
__device__ int    g_cnt[E_NUM];
__device__ float  g_probs_sum[E_NUM];
__device__ unsigned int g_ticket;

// ---------------- helpers ----------------------------------------------------
__device__ __forceinline__ float gelu_tanh(float x) {
    const float k0 = 0.7978845608028654f;
    float x3 = x * x * x;
    float t = tanhf(k0 * (x + 0.044715f * x3));
    return 0.5f * x * (1.0f + t);
}

// fp16 m16n8k16, fp32 accumulate
__device__ __forceinline__ void mma_f16(float* d, const uint32_t* a, const uint32_t* b) {
    asm volatile(
        "mma.sync.aligned.m16n8k16.row.col.f32.f16.f16.f32 "
        "{%0,%1,%2,%3}, {%4,%5,%6,%7}, {%8,%9}, {%0,%1,%2,%3};"
        : "+f"(d[0]), "+f"(d[1]), "+f"(d[2]), "+f"(d[3])
        : "r"(a[0]), "r"(a[1]), "r"(a[2]), "r"(a[3]), "r"(b[0]), "r"(b[1]));
}

__device__ __forceinline__ void cp_async16(uint32_t smem_dst, const void* gmem_src) {
    asm volatile("cp.async.cg.shared.global [%0], [%1], 16;\n" :: "r"(smem_dst), "l"(gmem_src));
}
__device__ __forceinline__ void cp_commit() {
    asm volatile("cp.async.commit_group;\n");
}
template <int N>
__device__ __forceinline__ void cp_wait() {
    asm volatile("cp.async.wait_group %0;\n" :: "n"(N));
}

// ---------------- init -------------------------------------------------------
__global__ void init_kernel() {
    int t = threadIdx.x;
    if (t < E_NUM) g_probs_sum[t] = 0.0f;
    if (t == 0) g_ticket = 0;
}

// ---------------- weight transpose + fp16 convert: [E][K][N] -> [E][N][K] -----
__global__ void transpose_h_kernel(const float* __restrict__ src,
                                   __half* __restrict__ dst, int K, int N) {
    __shared__ float t[64][65];
    int e = blockIdx.z;
    const float* s = src + (size_t)e * K * N;
    __half* d = dst + (size_t)e * N * K;
    int n0 = blockIdx.x * 64, k0 = blockIdx.y * 64;
    int tid = threadIdx.x;

    {
        int r = tid >> 4, c4 = tid & 15;
#pragma unroll
        for (int p = 0; p < 4; p++) {
            float4 v = *(const float4*)(s + (size_t)(k0 + r + p * 16) * N + n0 + c4 * 4);
            t[r + p * 16][c4 * 4 + 0] = v.x;
            t[r + p * 16][c4 * 4 + 1] = v.y;
            t[r + p * 16][c4 * 4 + 2] = v.z;
            t[r + p * 16][c4 * 4 + 3] = v.w;
        }
    }
    __syncthreads();
    {
        int n = tid >> 3, c8 = tid & 7;
#pragma unroll
        for (int p = 0; p < 2; p++) {
            int nn = n + p * 32;
            __half2 h[4];
#pragma unroll
            for (int j = 0; j < 4; j++)
                h[j] = __floats2half2_rn(t[c8 * 8 + 2 * j][nn], t[c8 * 8 + 2 * j + 1][nn]);
            *(uint4*)(d + (size_t)(n0 + nn) * K + k0 + c8 * 8) = *(uint4*)h;
        }
    }
}

// ---------------- scan body (run by the LAST gate block) -----------------------
__device__ void scan_body(float* __restrict__ d_out, int out_size,
                          unsigned long long* s0, unsigned long long* s1) {
    const int PER = 64;
    int t = threadIdx.x;
    int base = t * PER;

    int cnt[E_NUM];
#pragma unroll
    for (int e = 0; e < E_NUM; e++) cnt[e] = 0;
    for (int i = 0; i < PER; i++) cnt[g_eidx[base + i]]++;

    unsigned long long lo = 0, hi = 0;
#pragma unroll
    for (int e = 0; e < 4; e++) {
        lo |= (unsigned long long)cnt[e] << (16 * e);
        hi |= (unsigned long long)cnt[e + 4] << (16 * e);
    }

    s0[t] = lo; s1[t] = hi;
    __syncthreads();
    for (int off = 1; off < 256; off <<= 1) {
        unsigned long long v0 = 0, v1 = 0;
        if (t >= off) { v0 = s0[t - off]; v1 = s1[t - off]; }
        __syncthreads();
        s0[t] += v0; s1[t] += v1;
        __syncthreads();
    }
    unsigned long long p0 = (t > 0) ? s0[t - 1] : 0ULL;
    unsigned long long p1 = (t > 0) ? s1[t - 1] : 0ULL;

    int exc[E_NUM];
#pragma unroll
    for (int e = 0; e < 4; e++) {
        exc[e]     = (int)((p0 >> (16 * e)) & 0xffffULL);
        exc[e + 4] = (int)((p1 >> (16 * e)) & 0xffffULL);
    }
    for (int i = 0; i < PER; i++) {
        int s = base + i;
        int e = g_eidx[s];
        int pos = exc[e]++;
        g_loc[s] = (pos < CAP) ? (e * CAP + pos) : -1;
    }

    if (t == 0) {
        unsigned long long t0 = s0[255], t1 = s1[255];
        float sumload = 0.0f, load[E_NUM];
#pragma unroll
        for (int e = 0; e < 4; e++) {
            int c0 = (int)((t0 >> (16 * e)) & 0xffffULL);
            int c1 = (int)((t1 >> (16 * e)) & 0xffffULL);
            g_cnt[e]     = min(c0, CAP);
            g_cnt[e + 4] = min(c1, CAP);
            load[e]     = (float)min(c0, CAP);
            load[e + 4] = (float)min(c1, CAP);
        }
#pragma unroll
        for (int e = 0; e < E_NUM; e++) sumload += load[e];
        float fe[E_NUM], sfe = 0.0f;
#pragma unroll
        for (int e = 0; e < E_NUM; e++) { fe[e] = g_probs_sum[e] / (float)N_TOK; sfe += fe[e]; }
        float aux = 0.0f;
#pragma unroll
        for (int e = 0; e < E_NUM; e++) {
            float fn = fe[e] / (sfe + 1e-9f);
            float fa = load[e] / (sumload + 1e-9f);
            float d = fn - fa;
            aux += d * d;
        }
        aux = 0.01f * aux / (float)E_NUM;
        if (out_size > N_TOK * C_DIM)
            d_out[(size_t)N_TOK * C_DIM] = aux;
    }
}

// ---------------- gating + inline scan (last-block ticket) ---------------------
__global__ void gate_kernel(const float* __restrict__ x,
                            const float* __restrict__ w_gate,
                            const float* __restrict__ b_gate,
                            float* __restrict__ d_out, int out_size) {
    __shared__ unsigned long long sh0[256], sh1[256];  // reused: sprob then scan
    float* sprob = (float*)sh0;
    __shared__ int isLast;

    int tid = threadIdx.x;
    if (tid < E_NUM) sprob[tid] = 0.0f;
    __syncthreads();

    int warp = tid >> 5, lane = tid & 31;
    int n = blockIdx.x * 8 + warp;
    const float* xr = x + (size_t)n * C_DIM;

    float acc[E_NUM];
#pragma unroll
    for (int e = 0; e < E_NUM; e++) acc[e] = 0.0f;

    for (int c = lane; c < C_DIM; c += 32) {
        float xv = xr[c];
        const float4* w4 = (const float4*)(w_gate + (size_t)c * E_NUM);
        float4 wa = w4[0], wb = w4[1];
        acc[0] += xv * wa.x; acc[1] += xv * wa.y;
        acc[2] += xv * wa.z; acc[3] += xv * wa.w;
        acc[4] += xv * wb.x; acc[5] += xv * wb.y;
        acc[6] += xv * wb.z; acc[7] += xv * wb.w;
    }
#pragma unroll
    for (int e = 0; e < E_NUM; e++)
#pragma unroll
        for (int o = 16; o > 0; o >>= 1)
            acc[e] += __shfl_down_sync(0xffffffffu, acc[e], o);

    if (lane == 0) {
        float p[E_NUM];
        float mx = -1e30f;
#pragma unroll
        for (int e = 0; e < E_NUM; e++) { p[e] = acc[e] + b_gate[e]; mx = fmaxf(mx, p[e]); }
        float s = 0.0f;
#pragma unroll
        for (int e = 0; e < E_NUM; e++) { p[e] = expf(p[e] - mx); s += p[e]; }
        float inv = 1.0f / s;
#pragma unroll
        for (int e = 0; e < E_NUM; e++) p[e] *= inv;

        int i0 = 0;
#pragma unroll
        for (int e = 1; e < E_NUM; e++) if (p[e] > p[i0]) i0 = e;
        int i1 = (i0 == 0) ? 1 : 0;
#pragma unroll
        for (int e = 0; e < E_NUM; e++) if (e != i0 && p[e] > p[i1]) i1 = e;

        float w0 = p[i0], w1 = p[i1];
        float ws = w0 + w1 + 1e-9f;
        g_eidx[2 * n]     = i0;
        g_eidx[2 * n + 1] = i1;
        g_wf[2 * n]       = w0 / ws;
        g_wf[2 * n + 1]   = w1 / ws;
#pragma unroll
        for (int e = 0; e < E_NUM; e++) atomicAdd(&sprob[e], p[e]);
    }
    __syncthreads();
    if (tid < E_NUM) atomicAdd(&g_probs_sum[tid], sprob[tid]);

    // last-block ticket: the final block to finish runs the scan inline
    __threadfence();
    __syncthreads();
    if (tid == 0) {
        unsigned int rank = atomicAdd(&g_ticket, 1u);
        isLast = (rank == gridDim.x - 1);
    }
    __syncthreads();
    if (isLast) {
        __threadfence();   // acquire: make all blocks' g_eidx/g_probs_sum visible
        __syncthreads();
        scan_body(d_out, out_size, sh0, sh1);
    }
}

// ---------------- dispatch gather (fp16 convert at write) ----------------------
__global__ void dispatch_kernel(const float* __restrict__ x) {
    int s = blockIdx.x;
    int loc = g_loc[s];
    if (loc < 0) return;
    const float4* src = (const float4*)(x + ((size_t)(s >> 1)) * C_DIM);
    __half* dst = g_disp + (size_t)loc * C_DIM;
    int t = threadIdx.x;  // 128
    float4 v0 = src[2 * t];
    float4 v1 = src[2 * t + 1];
    __half2 h[4];
    h[0] = __floats2half2_rn(v0.x, v0.y);
    h[1] = __floats2half2_rn(v0.z, v0.w);
    h[2] = __floats2half2_rn(v1.x, v1.y);
    h[3] = __floats2half2_rn(v1.z, v1.w);
    *(uint4*)(dst + 8 * t) = *(uint4*)h;
}

// ---------------- grouped GEMM: fp16 mma.sync m16n8k16, GBK=64, 3 stages ------
#define GBM 128
#define GBN 128
#define GBK 64
#define GST 3
#define LDH 72                                     // 64 + 8 pad halfs
#define ASZH (GBM * LDH)                           // 9216 halfs
#define BSZH (GBN * LDH)
#define STG_BYTES ((ASZH + BSZH) * 2)              // 36864
#define GEMM_SMEM_BYTES (GST * STG_BYTES)          // 110592

template <bool GELU, typename OT>
__global__ __launch_bounds__(256, 2)
void gemm_kernel(const __half* __restrict__ A, const __half* __restrict__ Bt,
                 const float* __restrict__ bias, OT* __restrict__ Out,
                 int M, int N, int Kd) {
    int e = blockIdx.z;
    int bm = blockIdx.y, bn = blockIdx.x;
    if (bm * GBM >= g_cnt[e]) return;   // rows never read downstream

    extern __shared__ __half smem[];
    __half* Asm = smem;
    __half* Bsm = smem + GST * ASZH;

    const __half* Ae = A + (size_t)e * M * Kd;
    const __half* Be = Bt + (size_t)e * N * Kd;
    OT* Oe = Out + (size_t)e * M * N;

    int tid = threadIdx.x;
    int warp = tid >> 5, lane = tid & 31;
    int g = lane >> 2, tig = lane & 3;
    int wm = warp >> 2;
    int wn = warp & 3;

    uint32_t sA = (uint32_t)__cvta_generic_to_shared(Asm);
    uint32_t sB = (uint32_t)__cvta_generic_to_shared(Bsm);

    const int nK = Kd / GBK;

    auto issue = [&](int kt, int st) {
        uint32_t aBase = sA + (uint32_t)(st * ASZH) * 2;
        uint32_t bBase = sB + (uint32_t)(st * BSZH) * 2;
#pragma unroll
        for (int i = 0; i < 4; i++) {
            int ch = tid + 256 * i;
            int r = ch >> 3, c = (ch & 7) * 8;
            cp_async16(aBase + (uint32_t)(r * LDH + c) * 2,
                       Ae + (size_t)(bm * GBM + r) * Kd + kt * GBK + c);
        }
#pragma unroll
        for (int i = 0; i < 4; i++) {
            int ch = tid + 256 * i;
            int r = ch >> 3, c = (ch & 7) * 8;
            cp_async16(bBase + (uint32_t)(r * LDH + c) * 2,
                       Be + (size_t)(bn * GBN + r) * Kd + kt * GBK + c);
        }
        cp_commit();
    };

#pragma unroll
    for (int s = 0; s < GST - 1; s++) issue(s, s);

    float acc[4][4][4];
#pragma unroll
    for (int i = 0; i < 4; i++)
#pragma unroll
        for (int j = 0; j < 4; j++)
#pragma unroll
            for (int k = 0; k < 4; k++) acc[i][j][k] = 0.0f;

    for (int kt = 0; kt < nK; kt++) {
        if (kt < nK - 1) cp_wait<GST - 2>(); else cp_wait<0>();
        __syncthreads();

        int nt = kt + GST - 1;
        if (nt < nK) issue(nt, nt % GST);

        const __half* as = Asm + (kt % GST) * ASZH;
        const __half* bs = Bsm + (kt % GST) * BSZH;

#pragma unroll
        for (int kk = 0; kk < 4; kk++) {
            int kb = kk * 16;
            uint32_t af[4][4];
#pragma unroll
            for (int mt = 0; mt < 4; mt++) {
                int r0 = wm * 64 + mt * 16 + g;
                af[mt][0] = *(const uint32_t*)&as[r0 * LDH + kb + 2 * tig];
                af[mt][1] = *(const uint32_t*)&as[(r0 + 8) * LDH + kb + 2 * tig];
                af[mt][2] = *(const uint32_t*)&as[r0 * LDH + kb + 8 + 2 * tig];
                af[mt][3] = *(const uint32_t*)&as[(r0 + 8) * LDH + kb + 8 + 2 * tig];
            }
            uint32_t bf[4][2];
#pragma unroll
            for (int nt2 = 0; nt2 < 4; nt2++) {
                int c0 = wn * 32 + nt2 * 8 + g;
                bf[nt2][0] = *(const uint32_t*)&bs[c0 * LDH + kb + 2 * tig];
                bf[nt2][1] = *(const uint32_t*)&bs[c0 * LDH + kb + 8 + 2 * tig];
            }
#pragma unroll
            for (int mt = 0; mt < 4; mt++)
#pragma unroll
                for (int nt2 = 0; nt2 < 4; nt2++)
                    mma_f16(acc[mt][nt2], af[mt], bf[nt2]);
        }
    }

    // epilogue
#pragma unroll
    for (int mt = 0; mt < 4; mt++) {
        int r0 = bm * GBM + wm * 64 + mt * 16 + g;
#pragma unroll
        for (int nt2 = 0; nt2 < 4; nt2++) {
            int c0 = bn * GBN + wn * 32 + nt2 * 8 + 2 * tig;
            float bv0 = bias[(size_t)e * N + c0];
            float bv1 = bias[(size_t)e * N + c0 + 1];
            float v00 = acc[mt][nt2][0] + bv0;
            float v01 = acc[mt][nt2][1] + bv1;
            float v10 = acc[mt][nt2][2] + bv0;
            float v11 = acc[mt][nt2][3] + bv1;
            if (GELU) {
                v00 = gelu_tanh(v00); v01 = gelu_tanh(v01);
                v10 = gelu_tanh(v10); v11 = gelu_tanh(v11);
            }
            if constexpr (sizeof(OT) == 2) {
                *(__half2*)((__half*)Oe + (size_t)r0 * N + c0) = __floats2half2_rn(v00, v01);
                *(__half2*)((__half*)Oe + (size_t)(r0 + 8) * N + c0) = __floats2half2_rn(v10, v11);
            } else {
                *(float2*)((float*)Oe + (size_t)r0 * N + c0) = make_float2(v00, v01);
                *(float2*)((float*)Oe + (size_t)(r0 + 8) * N + c0) = make_float2(v10, v11);
            }
        }
    }
}

// ---------------- combine gather (half y inputs) -------------------------------
__global__ void combine_kernel(float* __restrict__ out) {
    int n = blockIdx.x;
    int l0 = g_loc[2 * n], l1 = g_loc[2 * n + 1];
    float w0 = (l0 >= 0) ? g_wf[2 * n] : 0.0f;
    float w1 = (l1 >= 0) ? g_wf[2 * n + 1] : 0.0f;
    const uint4* y0 = (const uint4*)(g_y + (size_t)max(l0, 0) * C_DIM);
    const uint4* y1 = (const uint4*)(g_y + (size_t)max(l1, 0) * C_DIM);
    float4* dst = (float4*)(out + (size_t)n * C_DIM);
    int t = threadIdx.x;  // 128 threads x 8 halfs

    uint4 pa = (l0 >= 0) ? y0[t] : make_uint4(0, 0, 0, 0);
    uint4 pb = (l1 >= 0) ? y1[t] : make_uint4(0, 0, 0, 0);
    const __half2* ha = (const __half2*)&pa;
    const __half2* hb = (const __half2*)&pb;
    float r[8];
#pragma unroll
    for (int j = 0; j < 4; j++) {
        float2 a = __half22float2(ha[j]);
        float2 b = __half22float2(hb[j]);
        r[2 * j]     = w0 * a.x + w1 * b.x;
        r[2 * j + 1] = w0 * a.y + w1 * b.y;
    }
    dst[2 * t]     = make_float4(r[0], r[1], r[2], r[3]);
    dst[2 * t + 1] = make_float4(r[4], r[5], r[6], r[7]);
}

// ---------------- launcher ----------------------------------------------------
extern "C" void kernel_launch(void* const* d_in, const int* in_sizes, int n_in,
                              void* d_out, int out_size) {
    const float* x      = (const float*)d_in[0];
    const float* w_gate = (const float*)d_in[1];
    const float* b_gate = (const float*)d_in[2];
    const float* W1     = (const float*)d_in[3];
    const float* b1     = (const float*)d_in[4];
    const float* W2     = (const float*)d_in[5];
    const float* b2     = (const float*)d_in[6];
    float* out = (float*)d_out;

    cudaFuncSetAttribute((const void*)gemm_kernel<true, __half>,
                         cudaFuncAttributeMaxDynamicSharedMemorySize, GEMM_SMEM_BYTES);
    cudaFuncSetAttribute((const void*)gemm_kernel<false, __half>,
                         cudaFuncAttributeMaxDynamicSharedMemorySize, GEMM_SMEM_BYTES);

    __half *disp = nullptr, *h = nullptr, *y = nullptr, *w1h = nullptr, *w2h = nullptr;
    cudaGetSymbolAddress((void**)&disp, g_disp);
    cudaGetSymbolAddress((void**)&h, g_h);
    cudaGetSymbolAddress((void**)&y, g_y);
    cudaGetSymbolAddress((void**)&w1h, g_W1h);
    cudaGetSymbolAddress((void**)&w2h, g_W2h);

    // fork a side stream for the weight transposes (independent of routing chain)
    cudaStream_t s2;
    cudaStreamCreateWithFlags(&s2, cudaStreamNonBlocking);
    cudaEvent_t evFork, evW1, evW2;
    cudaEventCreateWithFlags(&evFork, cudaEventDisableTiming);
    cudaEventCreateWithFlags(&evW1, cudaEventDisableTiming);
    cudaEventCreateWithFlags(&evW2, cudaEventDisableTiming);

    init_kernel<<<1, 32>>>();
    cudaEventRecord(evFork, 0);
    cudaStreamWaitEvent(s2, evFork, 0);

    // branch B (s2): W1 transpose (needed by GEMM1), then W2 (needed by GEMM2)
    {
        dim3 blk(256);
        dim3 t1(F_DIM / 64, C_DIM / 64, E_NUM);
        transpose_h_kernel<<<t1, blk, 0, s2>>>(W1, w1h, C_DIM, F_DIM);
        cudaEventRecord(evW1, s2);
        dim3 t2(C_DIM / 64, F_DIM / 64, E_NUM);
        transpose_h_kernel<<<t2, blk, 0, s2>>>(W2, w2h, F_DIM, C_DIM);
        cudaEventRecord(evW2, s2);
    }

    // branch A (main): gate (+inline scan in last block) -> dispatch
    gate_kernel<<<N_TOK / 8, 256>>>(x, w_gate, b_gate, out, out_size);
    dispatch_kernel<<<S_SLOTS, 128>>>(x);

    // join W1 before GEMM1; W2 transpose overlaps GEMM1 and joins before GEMM2
    cudaStreamWaitEvent(0, evW1, 0);
    {
        dim3 grid1(F_DIM / GBN, CAP / GBM, E_NUM);
        gemm_kernel<true, __half><<<grid1, 256, GEMM_SMEM_BYTES>>>(
            disp, w1h, b1, h, CAP, F_DIM, C_DIM);
    }
    cudaStreamWaitEvent(0, evW2, 0);
    {
        dim3 grid2(C_DIM / GBN, CAP / GBM, E_NUM);
        gemm_kernel<false, __half><<<grid2, 256, GEMM_SMEM_BYTES>>>(
            h, w2h, b2, y, CAP, C_DIM, F_DIM);
    }

    combine_kernel<<<N_TOK, 128>>>(out);

    cudaEventDestroy(evFork);
    cudaEventDestroy(evW1);
    cudaEventDestroy(evW2);
    cudaStreamDestroy(s2);
}